// round 1
// baseline (speedup 1.0000x reference)
#include <cuda_runtime.h>
#include <math.h>

// ---------------------------------------------------------------------------
// Problem constants
//   B=2, N_WAY=5, K_SHOT=5, C=64, H=W=10 (n=100), Q=75, PROJ=64, NHEAD=8 (dh=8)
//   ALPHAS = {8,4,2,1,0.5}  ->  sum_a exp(-a d) = t + t^2 + t^4 + t^8 + t^16,
//   with t = exp(-0.5 d).
// ---------------------------------------------------------------------------

#define NSUP_IMG 50     // 2*25
#define NQRY_IMG 150    // 2*75
#define NIMG 200
#define NPIX 100
#define CCH 64

// Padded channel-major feature scratch:
//   g_supT[b][w][c][512]  (points 0..499 valid, 500..511 zero)
//   g_qryT[b*75+q][c][128] (points 0..99 valid, 100..127 zero)
__device__ __align__(16) float g_supT[2 * 5 * 64 * 512];
__device__ __align__(16) float g_qryT[150 * 64 * 128];
__device__ __align__(16) float g_snS[2 * 5 * 512];
__device__ __align__(16) float g_snQ[150 * 128];
__device__ float g_accSS[10];
__device__ float g_accQQ[150];
__device__ float g_accQS[750];

#define ATT_SMEM_FLOATS (4 * 6400 + 256)
#define ATT_SMEM_BYTES (ATT_SMEM_FLOATS * sizeof(float))
#define GRAM_SMEM_BYTES (2 * 64 * 128 * sizeof(float))

// ---------------------------------------------------------------------------
// Zero the atomic accumulators (scratch feature pads are zeroed by attention).
// ---------------------------------------------------------------------------
__global__ void zero_accs() {
    int t = blockIdx.x * 256 + threadIdx.x;
    if (t < 10) g_accSS[t] = 0.f;
    if (t < 150) g_accQQ[t] = 0.f;
    if (t < 750) g_accQS[t] = 0.f;
}

// ---------------------------------------------------------------------------
// Attention + residual + channel-centering + L2 norm, fused per image.
// One block per image (200 blocks, 256 threads).
// ---------------------------------------------------------------------------
__global__ __launch_bounds__(256, 2)
void attention_kernel(const float* __restrict__ sup_x,
                      const float* __restrict__ qry_x,
                      const float* __restrict__ Wk,
                      const float* __restrict__ Wq,
                      const float* __restrict__ Wv) {
    extern __shared__ float sm[];
    float* xs = sm;             // [64][100] input
    float* ks = sm + 6400;      // [64][100] K
    float* qs = sm + 12800;     // [64][100] Q, later attention output y
    float* vs = sm + 19200;     // [64][100] V
    float* mean_s = sm + 25600; // [128]
    float* scal_s = sm + 25728; // [128]

    const int img = blockIdx.x;
    const int tid = threadIdx.x;
    const float* xg = (img < NSUP_IMG) ? (sup_x + (size_t)img * 6400)
                                       : (qry_x + (size_t)(img - NSUP_IMG) * 6400);

    for (int idx = tid; idx < 6400; idx += 256) xs[idx] = xg[idx];
    __syncthreads();

    // ---- 1x1 conv projections: out[o][n] = sum_c W[o][c] * x[c][n] ----
    {
        const int o = tid >> 2;
        const int n0 = (tid & 3) * 25;
        float ak[25], aq[25], av[25];
#pragma unroll
        for (int n = 0; n < 25; n++) { ak[n] = 0.f; aq[n] = 0.f; av[n] = 0.f; }
        for (int c = 0; c < 64; c++) {
            const float wk = __ldg(&Wk[o * 64 + c]);
            const float wq = __ldg(&Wq[o * 64 + c]);
            const float wv = __ldg(&Wv[o * 64 + c]);
            const float* xr = &xs[c * 100 + n0];
#pragma unroll
            for (int n = 0; n < 25; n++) {
                const float xv = xr[n];
                ak[n] += wk * xv;
                aq[n] += wq * xv;
                av[n] += wv * xv;
            }
        }
#pragma unroll
        for (int n = 0; n < 25; n++) {
            ks[o * 100 + n0 + n] = ak[n];
            qs[o * 100 + n0 + n] = aq[n];
            vs[o * 100 + n0 + n] = av[n];
        }
    }
    __syncthreads();

    // ---- softmax attention, 800 (head, pixel) tasks ----
    const float qscale = 0.3535533905932738f; // 1/sqrt(8)
    for (int task = tid; task < 800; task += 256) {
        const int h = task / 100;
        const int i = task - h * 100;
        float qv[8];
#pragma unroll
        for (int d = 0; d < 8; d++) qv[d] = qs[(h * 8 + d) * 100 + i] * qscale;

        float m = -1e30f;
        for (int j = 0; j < 100; j++) {
            float s = 0.f;
#pragma unroll
            for (int d = 0; d < 8; d++) s += qv[d] * ks[(h * 8 + d) * 100 + j];
            m = fmaxf(m, s);
        }
        float Z = 0.f;
        float acc[8];
#pragma unroll
        for (int d = 0; d < 8; d++) acc[d] = 0.f;
        for (int j = 0; j < 100; j++) {
            float s = 0.f;
#pragma unroll
            for (int d = 0; d < 8; d++) s += qv[d] * ks[(h * 8 + d) * 100 + j];
            const float e = __expf(s - m);
            Z += e;
#pragma unroll
            for (int d = 0; d < 8; d++) acc[d] += e * vs[(h * 8 + d) * 100 + j];
        }
        const float rz = 1.f / Z;
        // y[h*8+d][i] = attn_out + residual; each column owned by exactly one task
#pragma unroll
        for (int d = 0; d < 8; d++)
            qs[(h * 8 + d) * 100 + i] = acc[d] * rz + xs[(h * 8 + d) * 100 + i];
    }
    __syncthreads();

    // ---- destination mapping ----
    float* featDst;
    float* snDst;
    int ldd, padzero;
    if (img < NSUP_IMG) {
        const int b = img / 25, s = img % 25;
        const int way = s / 5, shot = s % 5;
        featDst = g_supT + ((size_t)(b * 5 + way) * 64) * 512 + shot * 100;
        snDst = g_snS + (b * 5 + way) * 512 + shot * 100;
        ldd = 512;
        padzero = (shot == 4) ? 12 : 0;
    } else {
        const int iq = img - NSUP_IMG;
        featDst = g_qryT + (size_t)iq * 64 * 128;
        snDst = g_snQ + iq * 128;
        ldd = 128;
        padzero = 28;
    }

    // ---- per-pixel centering + L2 norm stats ----
    for (int pix = tid; pix < 100; pix += 256) {
        float s = 0.f, s2 = 0.f;
        for (int c = 0; c < 64; c++) {
            const float v = qs[c * 100 + pix];
            s += v;
            s2 += v * v;
        }
        const float mu = s * (1.f / 64.f);
        float ss = s2 - s * mu;
        ss = fmaxf(ss, 0.f);
        const float sc = rsqrtf(ss + 1e-12f);
        mean_s[pix] = mu;
        scal_s[pix] = sc;
        snDst[pix] = ss / (ss + 1e-12f);
    }
    __syncthreads();

    // ---- write normalized features (channel-major) ----
    for (int idx = tid; idx < 6400; idx += 256) {
        const int c = idx / 100, pix = idx - c * 100;
        featDst[(size_t)c * ldd + pix] = (qs[c * 100 + pix] - mean_s[pix]) * scal_s[pix];
    }
    // ---- zero pad columns (so Gram kernel needs no load guards) ----
    if (padzero) {
        for (int t = tid; t < padzero; t += 256) snDst[100 + t] = 0.f;
        for (int t = tid; t < 64 * padzero; t += 256) {
            const int c = t / padzero, pp = t - c * padzero;
            featDst[(size_t)c * ldd + 100 + pp] = 0.f;
        }
    }
}

// ---------------------------------------------------------------------------
// Generic Gram + multi-scale-kernel-sum reduction.
// 128x128 output tile per block (256 threads, 8x8 microtile), K=64 one shot.
// mode 0: SS  grid(4,4,10)   A=B=sup(b,w) 500x500
// mode 1: QQ  grid(1,1,150)  A=B=qry(b,q) 100x100
// mode 2: QS  grid(4,1,750)  A=sup(b,w) 500  B=qry(b,q) 100
// ---------------------------------------------------------------------------
__global__ __launch_bounds__(256, 2)
void gram_kernel(int mode) {
    extern __shared__ float sh[];
    float* As = sh;            // [64][128]
    float* Bs = sh + 64 * 128; // [64][128]

    const int p = blockIdx.z;
    const float *A, *B, *snA, *snB;
    float* out;
    int lda, ldb, nA, nB, i0, j0;

    if (mode == 0) {
        A = g_supT + (size_t)p * 64 * 512; lda = 512; nA = 500;
        B = A; ldb = 512; nB = 500;
        snA = g_snS + p * 512; snB = snA;
        i0 = blockIdx.x * 128; j0 = blockIdx.y * 128;
        out = &g_accSS[p];
    } else if (mode == 1) {
        A = g_qryT + (size_t)p * 64 * 128; lda = 128; nA = 100;
        B = A; ldb = 128; nB = 100;
        snA = g_snQ + p * 128; snB = snA;
        i0 = 0; j0 = 0;
        out = &g_accQQ[p];
    } else {
        const int w = p % 5, bq = p / 5, b = bq / 75;
        A = g_supT + (size_t)((b * 5 + w) * 64) * 512; lda = 512; nA = 500;
        B = g_qryT + (size_t)bq * 64 * 128; ldb = 128; nB = 100;
        snA = g_snS + (b * 5 + w) * 512;
        snB = g_snQ + bq * 128;
        i0 = blockIdx.x * 128; j0 = 0;
        out = &g_accQS[p];
    }

    const int tid = threadIdx.x;
    // cooperative load: 64 rows x 128 cols each, float4
#pragma unroll
    for (int it = 0; it < 8; it++) {
        const int f = tid + it * 256; // 0..2047
        const int k = f >> 5;
        const int c4 = (f & 31) << 2;
        *(float4*)&As[k * 128 + c4] = *(const float4*)&A[(size_t)k * lda + i0 + c4];
        *(float4*)&Bs[k * 128 + c4] = *(const float4*)&B[(size_t)k * ldb + j0 + c4];
    }
    __syncthreads();

    const int tx = tid & 15, ty = tid >> 4;
    float acc[8][8];
#pragma unroll
    for (int u = 0; u < 8; u++)
#pragma unroll
        for (int v = 0; v < 8; v++) acc[u][v] = 0.f;

#pragma unroll 8
    for (int k = 0; k < 64; k++) {
        const float4 a0 = *(const float4*)&As[k * 128 + ty * 8];
        const float4 a1 = *(const float4*)&As[k * 128 + ty * 8 + 4];
        const float4 b0 = *(const float4*)&Bs[k * 128 + tx * 8];
        const float4 b1 = *(const float4*)&Bs[k * 128 + tx * 8 + 4];
        const float a[8] = {a0.x, a0.y, a0.z, a0.w, a1.x, a1.y, a1.z, a1.w};
        const float bb[8] = {b0.x, b0.y, b0.z, b0.w, b1.x, b1.y, b1.z, b1.w};
#pragma unroll
        for (int u = 0; u < 8; u++)
#pragma unroll
            for (int v = 0; v < 8; v++) acc[u][v] += a[u] * bb[v];
    }

    // epilogue: multi-scale gaussian kernel sum with validity mask
    const int ibase = i0 + ty * 8;
    const int jbase = j0 + tx * 8;
    float sb[8];
#pragma unroll
    for (int v = 0; v < 8; v++) sb[v] = snB[jbase + v];

    float ksum = 0.f;
#pragma unroll
    for (int u = 0; u < 8; u++) {
        if (ibase + u < nA) {
            const float sa = snA[ibase + u];
#pragma unroll
            for (int v = 0; v < 8; v++) {
                if (jbase + v < nB) {
                    float d = sa + sb[v] - 2.f * acc[u][v];
                    d = fmaxf(d, 0.f);
                    const float t = __expf(-0.5f * d);
                    const float t2 = t * t;
                    const float t4 = t2 * t2;
                    const float t8 = t4 * t4;
                    const float t16 = t8 * t8;
                    ksum += t + t2 + t4 + t8 + t16;
                }
            }
        }
    }

    // block reduction -> one atomicAdd
    __syncthreads(); // done reading As; reuse as reduction scratch
#pragma unroll
    for (int o = 16; o; o >>= 1) ksum += __shfl_xor_sync(0xffffffffu, ksum, o);
    if ((tid & 31) == 0) As[tid >> 5] = ksum;
    __syncthreads();
    if (tid == 0) {
        float tot = 0.f;
#pragma unroll
        for (int w = 0; w < 8; w++) tot += As[w];
        atomicAdd(out, tot);
    }
}

// ---------------------------------------------------------------------------
// Combine MMD terms -> logits -> log-softmax NLL mean (scalar).
// ---------------------------------------------------------------------------
__global__ void final_kernel(const int* __restrict__ qy, float* __restrict__ out) {
    __shared__ float red[160];
    const int r = threadIdx.x;
    float val = 0.f;
    if (r < 150) {
        const int b = r / 75;
        const float mq = (g_accQQ[r] - 500.f) * (1.f / 9900.f);
        float lg[5];
#pragma unroll
        for (int w = 0; w < 5; w++) {
            const float ms = (g_accSS[b * 5 + w] - 2500.f) * (1.f / 249500.f);
            const float msq = (-2.f / 50000.f) * g_accQS[r * 5 + w];
            lg[w] = -(ms + mq + msq) * (1.f / 12.5f);
        }
        float m = lg[0];
#pragma unroll
        for (int w = 1; w < 5; w++) m = fmaxf(m, lg[w]);
        float Z = 0.f;
#pragma unroll
        for (int w = 0; w < 5; w++) Z += expf(lg[w] - m);
        const float lse = m + logf(Z);
        const int y = qy[r];
        val = lse - lg[y]; // = -(logp[y])
    }
    red[r] = val;
    __syncthreads();
    if (r == 0) {
        float s = 0.f;
        for (int i = 0; i < 150; i++) s += red[i];
        out[0] = s * (1.f / 150.f);
    }
}

// ---------------------------------------------------------------------------
extern "C" void kernel_launch(void* const* d_in, const int* in_sizes, int n_in,
                              void* d_out, int out_size) {
    const float* sup = (const float*)d_in[0];
    const float* qry = (const float*)d_in[1];
    // d_in[2] = support_y (unused by the loss)
    const int* qy = (const int*)d_in[3];
    const float* Wk = (const float*)d_in[4];
    const float* Wq = (const float*)d_in[5];
    const float* Wv = (const float*)d_in[6];

    cudaFuncSetAttribute(attention_kernel,
                         cudaFuncAttributeMaxDynamicSharedMemorySize,
                         (int)ATT_SMEM_BYTES);
    cudaFuncSetAttribute(gram_kernel,
                         cudaFuncAttributeMaxDynamicSharedMemorySize,
                         (int)GRAM_SMEM_BYTES);

    zero_accs<<<4, 256>>>();
    attention_kernel<<<NIMG, 256, ATT_SMEM_BYTES>>>(sup, qry, Wk, Wq, Wv);
    gram_kernel<<<dim3(4, 4, 10), 256, GRAM_SMEM_BYTES>>>(0);
    gram_kernel<<<dim3(1, 1, 150), 256, GRAM_SMEM_BYTES>>>(1);
    gram_kernel<<<dim3(4, 1, 750), 256, GRAM_SMEM_BYTES>>>(2);
    final_kernel<<<1, 160>>>(qy, (float*)d_out);
}

// round 3
// speedup vs baseline: 2.2953x; 2.2953x over previous
#include <cuda_runtime.h>
#include <cuda_bf16.h>
#include <math.h>
#include <cstdint>

// ---------------------------------------------------------------------------
// Problem constants
//   B=2, N_WAY=5, K_SHOT=5, C=64, H=W=10 (n=100), Q=75, PROJ=64, NHEAD=8
//   ALPHAS = {8,4,2,1,0.5} -> sum_a exp(-a d) = t + t^2 + t^4 + t^8 + t^16,
//   t = exp(-0.5 d).
// Gram phase: portable tensor cores (ldmatrix + mma.sync m16n8k16 bf16->f32).
// ---------------------------------------------------------------------------

#define NSUP_IMG 50
#define NIMG 200

// bf16 features, point-major rows of 64 ch (=128B rows).
//   g_supB[b*5+w][512 pts][64]   (pts 500..511 zero)
//   g_qryB[b*75+q][128 pts][64]  (pts 100..127 zero)
__device__ __align__(16) __nv_bfloat16 g_supB[10 * 512 * 64];
__device__ __align__(16) __nv_bfloat16 g_qryB[150 * 128 * 64];
__device__ __align__(16) float g_snS[10 * 512];
__device__ __align__(16) float g_snQ[150 * 128];
__device__ float g_accSS[10];
__device__ float g_accQQ[150];
__device__ float g_accQS[750];

#define ATT_SMEM_FLOATS (4 * 6400 + 256)
#define ATT_SMEM_BYTES (ATT_SMEM_FLOATS * sizeof(float))

#define SMEM_SWIZZLE_128B(off) ((off) ^ (((off) >> 3) & 0x70))

__device__ __forceinline__ uint32_t smem_to_u32(const void* p) {
    uint32_t a;
    asm("{ .reg .u64 t; cvta.to.shared.u64 t, %1; cvt.u32.u64 %0, t; }"
        : "=r"(a) : "l"(p));
    return a;
}
__device__ __forceinline__ void ldsm_x4(uint32_t& r0, uint32_t& r1,
                                        uint32_t& r2, uint32_t& r3,
                                        uint32_t addr) {
    asm volatile("ldmatrix.sync.aligned.m8n8.x4.shared.b16 {%0,%1,%2,%3}, [%4];"
                 : "=r"(r0), "=r"(r1), "=r"(r2), "=r"(r3) : "r"(addr));
}
__device__ __forceinline__ void ldsm_x2(uint32_t& r0, uint32_t& r1,
                                        uint32_t addr) {
    asm volatile("ldmatrix.sync.aligned.m8n8.x2.shared.b16 {%0,%1}, [%2];"
                 : "=r"(r0), "=r"(r1) : "r"(addr));
}
__device__ __forceinline__ void mma16816(float* d, const uint32_t* a,
                                         const uint32_t* b) {
    asm volatile(
        "mma.sync.aligned.m16n8k16.row.col.f32.bf16.bf16.f32 "
        "{%0,%1,%2,%3}, {%4,%5,%6,%7}, {%8,%9}, {%0,%1,%2,%3};"
        : "+f"(d[0]), "+f"(d[1]), "+f"(d[2]), "+f"(d[3])
        : "r"(a[0]), "r"(a[1]), "r"(a[2]), "r"(a[3]), "r"(b[0]), "r"(b[1]));
}

// ---------------------------------------------------------------------------
__global__ void zero_accs() {
    int t = blockIdx.x * 256 + threadIdx.x;
    if (t < 10) g_accSS[t] = 0.f;
    if (t < 150) g_accQQ[t] = 0.f;
    if (t < 750) g_accQS[t] = 0.f;
}

// ---------------------------------------------------------------------------
// Attention + residual + centering + L2 norm + bf16 feature emit.
// One block per image (200 blocks, 256 threads).
// ---------------------------------------------------------------------------
__global__ __launch_bounds__(256, 2)
void attention_kernel(const float* __restrict__ sup_x,
                      const float* __restrict__ qry_x,
                      const float* __restrict__ Wk,
                      const float* __restrict__ Wq,
                      const float* __restrict__ Wv) {
    extern __shared__ float sm[];
    float* xs = sm;             // [64][100]
    float* qs = sm + 6400;      // [64][100] Q proj, later attention output y
    float* kT = sm + 12800;     // [8][100][8]  (h, j, d) - d contiguous
    float* vT = sm + 19200;     // [8][100][8]
    float* mean_s = sm + 25600; // [128]
    float* scal_s = sm + 25728; // [128]

    const int img = blockIdx.x;
    const int tid = threadIdx.x;
    const float* xg = (img < NSUP_IMG) ? (sup_x + (size_t)img * 6400)
                                       : (qry_x + (size_t)(img - NSUP_IMG) * 6400);

    for (int idx = tid; idx < 6400; idx += 256) xs[idx] = xg[idx];
    __syncthreads();

    // ---- 1x1 conv projections ----
    {
        const int o = tid >> 2;         // 0..63
        const int h = o >> 3, d = o & 7;
        const int n0 = (tid & 3) * 25;
        float ak[25], aq[25], av[25];
#pragma unroll
        for (int n = 0; n < 25; n++) { ak[n] = 0.f; aq[n] = 0.f; av[n] = 0.f; }
        for (int c = 0; c < 64; c++) {
            const float wk = __ldg(&Wk[o * 64 + c]);
            const float wq = __ldg(&Wq[o * 64 + c]);
            const float wv = __ldg(&Wv[o * 64 + c]);
            const float* xr = &xs[c * 100 + n0];
#pragma unroll
            for (int n = 0; n < 25; n++) {
                const float xv = xr[n];
                ak[n] += wk * xv;
                aq[n] += wq * xv;
                av[n] += wv * xv;
            }
        }
#pragma unroll
        for (int n = 0; n < 25; n++) {
            kT[h * 800 + (n0 + n) * 8 + d] = ak[n];
            vT[h * 800 + (n0 + n) * 8 + d] = av[n];
            qs[o * 100 + n0 + n] = aq[n];
        }
    }
    __syncthreads();

    // ---- softmax attention: 800 (head, pixel) tasks ----
    const float qscale = 0.3535533905932738f;
    for (int task = tid; task < 800; task += 256) {
        const int h = task / 100;
        const int i = task - h * 100;
        const float4* kh = (const float4*)(kT + h * 800);
        const float4* vh = (const float4*)(vT + h * 800);
        float qv[8];
#pragma unroll
        for (int d = 0; d < 8; d++) qv[d] = qs[(h * 8 + d) * 100 + i] * qscale;

        float m = -1e30f;
        for (int j = 0; j < 100; j++) {
            const float4 k0 = kh[j * 2], k1 = kh[j * 2 + 1];
            float s = qv[0] * k0.x + qv[1] * k0.y + qv[2] * k0.z + qv[3] * k0.w +
                      qv[4] * k1.x + qv[5] * k1.y + qv[6] * k1.z + qv[7] * k1.w;
            m = fmaxf(m, s);
        }
        float Z = 0.f;
        float acc[8];
#pragma unroll
        for (int d = 0; d < 8; d++) acc[d] = 0.f;
        for (int j = 0; j < 100; j++) {
            const float4 k0 = kh[j * 2], k1 = kh[j * 2 + 1];
            float s = qv[0] * k0.x + qv[1] * k0.y + qv[2] * k0.z + qv[3] * k0.w +
                      qv[4] * k1.x + qv[5] * k1.y + qv[6] * k1.z + qv[7] * k1.w;
            const float e = __expf(s - m);
            Z += e;
            const float4 v0 = vh[j * 2], v1 = vh[j * 2 + 1];
            acc[0] += e * v0.x; acc[1] += e * v0.y;
            acc[2] += e * v0.z; acc[3] += e * v0.w;
            acc[4] += e * v1.x; acc[5] += e * v1.y;
            acc[6] += e * v1.z; acc[7] += e * v1.w;
        }
        const float rz = 1.f / Z;
#pragma unroll
        for (int d = 0; d < 8; d++)
            qs[(h * 8 + d) * 100 + i] = acc[d] * rz + xs[(h * 8 + d) * 100 + i];
    }
    __syncthreads();

    // ---- destination mapping ----
    __nv_bfloat16* featDst;
    float* snDst;
    int padrows;
    if (img < NSUP_IMG) {
        const int b = img / 25, s = img % 25;
        const int way = s / 5, shot = s % 5;
        featDst = g_supB + ((size_t)(b * 5 + way) * 512 + shot * 100) * 64;
        snDst = g_snS + (b * 5 + way) * 512 + shot * 100;
        padrows = (shot == 4) ? 12 : 0;
    } else {
        const int iq = img - NSUP_IMG;
        featDst = g_qryB + (size_t)iq * 128 * 64;
        snDst = g_snQ + iq * 128;
        padrows = 28;
    }

    // ---- per-pixel stats; sn computed from bf16-ROUNDED features ----
    for (int pix = tid; pix < 100; pix += 256) {
        float s = 0.f, s2 = 0.f;
        for (int c = 0; c < 64; c++) {
            const float v = qs[c * 100 + pix];
            s += v;
            s2 += v * v;
        }
        const float mu = s * (1.f / 64.f);
        float ss = fmaxf(s2 - s * mu, 0.f);
        const float sc = rsqrtf(ss + 1e-12f);
        mean_s[pix] = mu;
        scal_s[pix] = sc;
        float sb = 0.f;
        for (int c = 0; c < 64; c++) {
            const float f = (qs[c * 100 + pix] - mu) * sc;
            const float fb = __bfloat162float(__float2bfloat16(f));
            sb += fb * fb;
        }
        snDst[pix] = sb;
    }
    __syncthreads();

    // ---- write bf16 features, point-major ----
    for (int idx = tid; idx < 6400; idx += 256) {
        const int pt = idx >> 6, c = idx & 63;
        const float f = (qs[c * 100 + pt] - mean_s[pt]) * scal_s[pt];
        featDst[(size_t)pt * 64 + c] = __float2bfloat16(f);
    }
    if (padrows) {
        for (int t = tid; t < padrows; t += 256) snDst[100 + t] = 0.f;
        for (int t = tid; t < padrows * 64; t += 256)
            featDst[100 * 64 + t] = __float2bfloat16(0.f);
    }
}

// ---------------------------------------------------------------------------
// Tensor-core Gram + multi-scale kernel-sum. 128x128x64 tile per block,
// 8 warps (2x4), each warp 64x32 via mma.sync m16n8k16 bf16.
// Block decode (1D grid of 3310):
//   [0,160)    SS: p=bid/16, 4x4 tiles over 512x512
//   [160,310)  QQ: p=bid-160
//   [310,3310) QS: r=bid-310, p=r/4, i0=(r%4)*128
// ---------------------------------------------------------------------------
__global__ __launch_bounds__(256)
void gram_tc() {
    __shared__ __align__(16) char smA[16384];   // [128 pts][64 ch] bf16, swizzled
    __shared__ __align__(16) char smB[16384];
    __shared__ float snAs[128];
    __shared__ float snBs[128];
    __shared__ float red[8];

    const int tid = threadIdx.x;
    const int wid = tid >> 5, l = tid & 31;
    const int bid = blockIdx.x;

    const __nv_bfloat16 *Ag, *Bg;
    const float *snAg, *snBg;
    float* outp;
    int i0, j0, nA, nB;
    if (bid < 160) {
        const int p = bid >> 4, t = bid & 15;
        i0 = (t & 3) * 128; j0 = (t >> 2) * 128;
        Ag = g_supB + (size_t)p * 512 * 64; Bg = Ag;
        snAg = g_snS + p * 512; snBg = snAg;
        nA = 500; nB = 500;
        outp = &g_accSS[p];
    } else if (bid < 310) {
        const int p = bid - 160;
        i0 = 0; j0 = 0;
        Ag = g_qryB + (size_t)p * 128 * 64; Bg = Ag;
        snAg = g_snQ + p * 128; snBg = snAg;
        nA = 100; nB = 100;
        outp = &g_accQQ[p];
    } else {
        const int r = bid - 310;
        const int p = r >> 2;
        i0 = (r & 3) * 128; j0 = 0;
        const int w = p % 5, bq = p / 5, b = bq / 75;
        Ag = g_supB + (size_t)(b * 5 + w) * 512 * 64;
        Bg = g_qryB + (size_t)bq * 128 * 64;
        snAg = g_snS + (b * 5 + w) * 512;
        snBg = g_snQ + bq * 128;
        nA = 500; nB = 100;
        outp = &g_accQS[p];
    }

    if (tid < 128) {
        snAs[tid] = snAg[i0 + tid];   // padded arrays -> always in-bounds
        snBs[tid] = snBg[j0 + tid];
    }

    // ---- load tiles into swizzled smem (128B rows) ----
    const char* Arow = (const char*)(Ag + (size_t)i0 * 64);
    const char* Brow = (const char*)(Bg + (size_t)j0 * 64);
#pragma unroll
    for (int it = 0; it < 4; it++) {
        const int idx = it * 256 + tid;        // 0..1023 (16B chunks)
        const int off = (idx >> 3) * 128 + (idx & 7) * 16;
        const uint4 va = *(const uint4*)(Arow + off);
        const uint4 vb = *(const uint4*)(Brow + off);
        const int sw = SMEM_SWIZZLE_128B(off);
        *(uint4*)(smA + sw) = va;
        *(uint4*)(smB + sw) = vb;
    }
    __syncthreads();

    // ---- warp tile: warp (wm, wn) -> 64x32 at (wm*64, wn*32) ----
    const int wm = wid & 1, wn = wid >> 1;
    const uint32_t aBase = smem_to_u32(smA);
    const uint32_t bBase = smem_to_u32(smB);

    float acc[4][4][4];
#pragma unroll
    for (int mi = 0; mi < 4; mi++)
#pragma unroll
        for (int ni = 0; ni < 4; ni++)
#pragma unroll
            for (int e = 0; e < 4; e++) acc[mi][ni][e] = 0.f;

    // per-lane ldmatrix address components
    const int arow_l = l & 15;          // row within 16
    const int acol_l = ((l >> 4) & 1) * 16;
    const int brow_l = l & 7;           // row within 8
    const int bcol_l = ((l >> 3) & 1) * 16;

#pragma unroll
    for (int ki = 0; ki < 4; ki++) {
        uint32_t af[4][4], bf[4][2];
#pragma unroll
        for (int mi = 0; mi < 4; mi++) {
            const int off = (wm * 64 + mi * 16 + arow_l) * 128 + ki * 32 + acol_l;
            ldsm_x4(af[mi][0], af[mi][1], af[mi][2], af[mi][3],
                    aBase + SMEM_SWIZZLE_128B(off));
        }
#pragma unroll
        for (int ni = 0; ni < 4; ni++) {
            const int off = (wn * 32 + ni * 8 + brow_l) * 128 + ki * 32 + bcol_l;
            ldsm_x2(bf[ni][0], bf[ni][1], bBase + SMEM_SWIZZLE_128B(off));
        }
#pragma unroll
        for (int mi = 0; mi < 4; mi++)
#pragma unroll
            for (int ni = 0; ni < 4; ni++)
                mma16816(acc[mi][ni], af[mi], bf[ni]);
    }

    // ---- epilogue: d = snA + snB - 2*dot -> sum of gaussians, masked ----
    int jmax = nB - j0; if (jmax > 128) jmax = 128;
    const int qrow = l >> 2, qcol = (l & 3) * 2;

    float ksum = 0.f;
#pragma unroll
    for (int mi = 0; mi < 4; mi++) {
#pragma unroll
        for (int half = 0; half < 2; half++) {
            const int iloc = wm * 64 + mi * 16 + qrow + half * 8;
            if (i0 + iloc < nA) {
                const float sa = snAs[iloc];
#pragma unroll
                for (int ni = 0; ni < 4; ni++) {
                    const int jl = wn * 32 + ni * 8 + qcol;
                    if (jl < jmax) {  // jmax even -> pair validity identical
#pragma unroll
                        for (int e = 0; e < 2; e++) {
                            const float dot = acc[mi][ni][half * 2 + e];
                            float dd = sa + snBs[jl + e] - 2.f * dot;
                            dd = fmaxf(dd, 0.f);
                            const float t = __expf(-0.5f * dd);
                            const float t2 = t * t;
                            const float t4 = t2 * t2;
                            const float t8 = t4 * t4;
                            const float t16 = t8 * t8;
                            ksum += t + t2 + t4 + t8 + t16;
                        }
                    }
                }
            }
        }
    }

#pragma unroll
    for (int o = 16; o; o >>= 1) ksum += __shfl_xor_sync(0xffffffffu, ksum, o);
    if (l == 0) red[wid] = ksum;
    __syncthreads();
    if (tid == 0) {
        float tot = 0.f;
#pragma unroll
        for (int w = 0; w < 8; w++) tot += red[w];
        atomicAdd(outp, tot);
    }
}

// ---------------------------------------------------------------------------
__global__ void final_kernel(const int* __restrict__ qy, float* __restrict__ out) {
    __shared__ float red[160];
    const int r = threadIdx.x;
    float val = 0.f;
    if (r < 150) {
        const int b = r / 75;
        const float mq = (g_accQQ[r] - 500.f) * (1.f / 9900.f);
        float lg[5];
#pragma unroll
        for (int w = 0; w < 5; w++) {
            const float ms = (g_accSS[b * 5 + w] - 2500.f) * (1.f / 249500.f);
            const float msq = (-2.f / 50000.f) * g_accQS[r * 5 + w];
            lg[w] = -(ms + mq + msq) * (1.f / 12.5f);
        }
        float m = lg[0];
#pragma unroll
        for (int w = 1; w < 5; w++) m = fmaxf(m, lg[w]);
        float Z = 0.f;
#pragma unroll
        for (int w = 0; w < 5; w++) Z += expf(lg[w] - m);
        const float lse = m + logf(Z);
        val = lse - lg[qy[r]];
    }
    red[r] = val;
    __syncthreads();
    if (r == 0) {
        float s = 0.f;
        for (int i = 0; i < 150; i++) s += red[i];
        out[0] = s * (1.f / 150.f);
    }
}

// ---------------------------------------------------------------------------
extern "C" void kernel_launch(void* const* d_in, const int* in_sizes, int n_in,
                              void* d_out, int out_size) {
    const float* sup = (const float*)d_in[0];
    const float* qry = (const float*)d_in[1];
    const int* qy = (const int*)d_in[3];
    const float* Wk = (const float*)d_in[4];
    const float* Wq = (const float*)d_in[5];
    const float* Wv = (const float*)d_in[6];

    cudaFuncSetAttribute(attention_kernel,
                         cudaFuncAttributeMaxDynamicSharedMemorySize,
                         (int)ATT_SMEM_BYTES);

    zero_accs<<<4, 256>>>();
    attention_kernel<<<NIMG, 256, ATT_SMEM_BYTES>>>(sup, qry, Wk, Wq, Wv);
    gram_tc<<<3310, 256>>>();
    final_kernel<<<1, 160>>>(qy, (float*)d_out);
}